// round 15
// baseline (speedup 1.0000x reference)
#include <cuda_runtime.h>

#define NK 5000
#define BB 512
#define TT 100
#define HS 256   // hash slots (power of 2), load factor <= 99/256

__device__ float g_init[NK];           // sigmoid(logits[:,4]), built by kernel1
__device__ int   g_fixIdx[BB * TT];    // per-(row,t): state index to patch, -1 if none
__device__ float g_fixVal[BB * TT];    // patch value

__device__ __forceinline__ float sigm(float x) {
    return 1.f / (1.f + __expf(-x));
}

__device__ __forceinline__ int hashk(int k) {
    return (int)(((unsigned)k * 2654435761u) >> 20) & (HS - 1);
}

// highest set bit index <= cap over a 4x32 mask, 0 if none (bit 0 never set)
__device__ __forceinline__ int hibit_le(const unsigned m[4], int cap) {
    const int w = cap >> 5;
    const unsigned inc = (2u << (cap & 31)) - 1u;
    int r = 0;
    #pragma unroll
    for (int j = 3; j >= 0; --j) {
        unsigned mm = (j > w) ? 0u : ((j == w) ? (m[j] & inc) : m[j]);
        if (mm && r == 0) r = (j << 5) + 31 - __clz(mm);
    }
    return r;
}

// Phase 1: gathers + dependency-forest resolution + probs + fixup list.
// One CTA (128 threads) per batch row. Blocks 0..39 additionally materialize
// g_init (125 entries each) — done once chip-wide instead of per-CTA.
__global__ __launch_bounds__(128, 1) void bkt_compute(
    const int* __restrict__ prev_kc,
    const int* __restrict__ curr_kc,
    const int* __restrict__ prev_corr,
    const float* __restrict__ logits,
    float* __restrict__ out)
{
    __shared__ int      s_hkey[HS];
    __shared__ unsigned s_hmask[HS][4];
    __shared__ int      s_prev[TT];
    __shared__ float    s_pred[TT];
    __shared__ int      s_wmax[4];

    const int b = blockIdx.x;
    const int t = threadIdx.x;
    const bool active = (t < TT);

    // Side job: build the shared init vector (40 blocks x 125 entries).
    if (b < 40 && t < 125) {
        const int k = b * 125 + t;
        g_init[k] = sigm(logits[k * 5 + 4]);
    }

    // hash init (2 slots per thread)
    #pragma unroll
    for (int j = 0; j < 2; ++j) {
        const int s = t + j * 128;
        s_hkey[s] = -1;
        s_hmask[s][0] = 0u; s_hmask[s][1] = 0u;
        s_hmask[s][2] = 0u; s_hmask[s][3] = 0u;
    }

    // ---- Phase A: gathers, sigmoids, per-thread chain constants ----
    int   pk = -1, ck = 0;
    float Cx = 0.f, Cy = 0.f, Cz = 0.f, Cw = 0.f;
    float Px = 0.f, Py = 0.f, skill0 = 0.f, ckinit = 0.f;
    if (active) {
        ck = curr_kc[b * TT + t];
        if (t >= 1) {
            pk = prev_kc[b * TT + t];
            const int c = prev_corr[b * TT + t];
            const float* rp = logits + pk * 5;
            const float pvx = sigm(rp[0]);
            const float pvy = sigm(rp[1]);
            const float pvz = sigm(rp[2]);
            const float pvw = sigm(rp[3]);
            skill0 = sigm(rp[4]);
            const float p2 = c ? pvz : 1.f - pvz;   // p_out[0]
            const float p3 = c ? pvw : 1.f - pvw;   // p_out[1]
            Cx = p2;  Cy = p3 - p2;  Cz = pvx;
            Cw = (1.f - pvy - pvx) * p3;            // pred = Cz + Cw*sk/den
        }
        const float* cp = logits + ck * 5;
        const float cvz = sigm(cp[2]);
        const float cvw = sigm(cp[3]);
        ckinit = sigm(cp[4]);
        Px = cvz;  Py = cvw - cvz;                  // prob = fma(cs,Py,Px)
    }
    __syncthreads();                                // hash zeroed

    // ---- Insert: claim slot for pk, set timestep bit ----
    int myslot = -1;
    if (active && t >= 1) {
        int s = hashk(pk);
        while (true) {
            const int old = atomicCAS(&s_hkey[s], -1, pk);
            if (old == -1 || old == pk) break;
            s = (s + 1) & (HS - 1);
        }
        myslot = s;
        atomicOr(&s_hmask[s][t >> 5], 1u << (t & 31));
    }
    __syncthreads();                                // table stable

    // ---- Lookups: prev / islast (own slot), tc (probe ck) ----
    int prev = 0, tc = 0;
    bool islast = true;
    if (active) {
        if (t >= 1) {
            unsigned m[4];
            m[0] = s_hmask[myslot][0]; m[1] = s_hmask[myslot][1];
            m[2] = s_hmask[myslot][2]; m[3] = s_hmask[myslot][3];
            if (t > 1) prev = hibit_le(m, t - 1);
            const int w = t >> 5;
            unsigned above = m[w] & ~((2u << (t & 31)) - 1u);
            #pragma unroll
            for (int j = 0; j < 4; ++j)
                if (j > w) above |= m[j];
            islast = (above == 0u);
            s_prev[t] = prev;
        }
        {   // tc: probe for ck (absent -> 0 -> init)
            int s = hashk(ck), fs = -1;
            while (true) {
                const int kk = s_hkey[s];
                if (kk == ck) { fs = s; break; }
                if (kk == -1) break;
                s = (s + 1) & (HS - 1);
            }
            if (fs >= 0) {
                unsigned m2[4];
                m2[0] = s_hmask[fs][0]; m2[1] = s_hmask[fs][1];
                m2[2] = s_hmask[fs][2]; m2[3] = s_hmask[fs][3];
                tc = hibit_le(m2, t);
            }
        }
    }
    __syncthreads();                                // s_prev ready

    // ---- Depth in the dependency forest ----
    int depth = 0;
    if (active && t >= 1)
        for (int c2 = prev; c2 != 0; c2 = s_prev[c2]) depth++;
    const int wm = __reduce_max_sync(0xffffffffu, depth);
    if ((t & 31) == 0) s_wmax[t >> 5] = wm;
    __syncthreads();
    const int maxd = max(max(s_wmax[0], s_wmax[1]),
                         max(s_wmax[2], s_wmax[3]));

    // ---- Rounds: resolve preds in depth order ----
    float myPred = 0.f;
    for (int r = 0; r <= maxd; ++r) {
        if (active && t >= 1 && depth == r) {
            const float sk  = prev ? s_pred[prev] : skill0;
            const float den = fmaf(Cy, sk, Cx);
            myPred = Cz + __fdividef(Cw * sk, den);
            s_pred[t] = myPred;
        }
        __syncthreads();
    }

    // ---- Probs + fixup list (compact, deterministic every replay) ----
    if (active) {
        const float cs = tc ? s_pred[tc] : ckinit;
        out[b * TT + t] = fmaf(cs, Py, Px);
        const bool doFix = (t >= 1) && islast;
        g_fixIdx[b * TT + t] = doFix ? pk : -1;
        g_fixVal[b * TT + t] = myPred;
    }
}

// Phase 2: pure streaming. Copy the shared init vector to every row
// (LDG.128 L2-broadcast + STG.128), then apply the <=99 per-row patches.
__global__ __launch_bounds__(256, 1) void bkt_state(float* __restrict__ out)
{
    const int b = blockIdx.x;
    const int tid = threadIdx.x;
    float* stateOut = out + BB * TT + b * NK;       // 16B-aligned for every b

    const float4* gi4 = (const float4*)g_init;
    float4* so4 = (float4*)stateOut;
    #pragma unroll
    for (int k4 = tid; k4 < NK / 4; k4 += 256) so4[k4] = gi4[k4];
    __syncthreads();                                // copies visible block-wide

    if (tid < TT) {
        const int ix = g_fixIdx[b * TT + tid];
        if (ix >= 0) stateOut[ix] = g_fixVal[b * TT + tid];
    }
}

extern "C" void kernel_launch(void* const* d_in, const int* in_sizes, int n_in,
                              void* d_out, int out_size) {
    const int*   prev_kc   = (const int*)d_in[0];
    const int*   curr_kc   = (const int*)d_in[1];
    const int*   prev_corr = (const int*)d_in[2];
    const float* logits    = (const float*)d_in[3];
    float*       out       = (float*)d_out;

    bkt_compute<<<BB, 128>>>(prev_kc, curr_kc, prev_corr, logits, out);
    bkt_state<<<BB, 256>>>(out);
}